// round 8
// baseline (speedup 1.0000x reference)
#include <cuda_runtime.h>

// Problem dims (fixed for SNN_Vanilla_11630771437863)
#define BB 256      // batch
#define TT 100      // timesteps
#define DD 2312     // input dim (2*34*34)
#define HH 1000     // hidden
#define OO 10       // output

// Scratch: cur1_all stored [B][T][H] (b-major so scan CTA b reads contiguously)
__device__ float g_cur1[(size_t)BB * TT * HH];   // 102.4 MB

// ---------------------------------------------------------------------------
// Kernel 1: cur1[r][n] = sum_k A[r][k] * W1[n][k] + b1[n]
// Accumulation order matched to XLA-CPU / Eigen SINGLE-THREADED gebp blocking
// (aarch64 NEON traits mr=12, nr=4, default l1=16KB -> max_kc=248, then the
// ST branch BALANCES panels):
//   kc = 248 - 8*((247 - (2312%248)) / (8*(2312/248+1))) = 232
//   panels: 9 x 232 + 224   (boundaries every 29 k-tiles of 8)
//   - within a panel: single-accumulator ascending-k FMA chain from 0
//   - panels added into the running total sequentially (first panel exact)
//   - then ONE fp32 bias add.
// ---------------------------------------------------------------------------
__global__ __launch_bounds__(256) void gemm1_kernel(
    const float* __restrict__ A,
    const float* __restrict__ W,
    const float* __restrict__ b1)
{
    __shared__ float As[2][8][128];
    __shared__ float Bs[2][8][64];

    const int bm = blockIdx.y;          // 0..199
    const int bn = blockIdx.x;          // 0..15
    const int tid = threadIdx.x;

    const int tm = (tid >> 4) * 8;      // M offset in tile
    const int tn = (tid & 15) * 4;      // N offset in tile

    const int a_row = tid >> 1;         // 0..127
    const int a_k4  = (tid & 1) * 4;    // 0 or 4
    const int nbase = bn * 64;

    const float* Ab = A + (size_t)(bm * 128) * DD;

    float tot[8][4];   // running sum over panels
    float acc[8][4];   // current panel partial
#pragma unroll
    for (int i = 0; i < 8; i++)
#pragma unroll
        for (int j = 0; j < 4; j++) { tot[i][j] = 0.f; acc[i][j] = 0.f; }

    // prologue: load k-tile 0 into buffer 0
    {
        float4 av = *(const float4*)(Ab + (size_t)a_row * DD + a_k4);
        As[0][a_k4 + 0][a_row] = av.x;
        As[0][a_k4 + 1][a_row] = av.y;
        As[0][a_k4 + 2][a_row] = av.z;
        As[0][a_k4 + 3][a_row] = av.w;
        if (tid < 128) {
            int n = nbase + a_row;
            float4 bv = make_float4(0.f, 0.f, 0.f, 0.f);
            if (n < HH) bv = *(const float4*)(W + (size_t)n * DD + a_k4);
            Bs[0][a_k4 + 0][a_row] = bv.x;
            Bs[0][a_k4 + 1][a_row] = bv.y;
            Bs[0][a_k4 + 2][a_row] = bv.z;
            Bs[0][a_k4 + 3][a_row] = bv.w;
        }
    }
    __syncthreads();

    const int KITER = DD / 8;   // 289 exactly
    int buf = 0;
    for (int kt = 0; kt < KITER; ++kt) {
        const int nb = buf ^ 1;
        float4 av, bv;
        bool have_next = (kt + 1 < KITER);
        if (have_next) {
            int k0 = (kt + 1) * 8;
            av = *(const float4*)(Ab + (size_t)a_row * DD + k0 + a_k4);
            if (tid < 128) {
                int n = nbase + a_row;
                bv = make_float4(0.f, 0.f, 0.f, 0.f);
                if (n < HH) bv = *(const float4*)(W + (size_t)n * DD + k0 + a_k4);
            }
        }

        // compute on current buffer: kk ascending -> k strictly ascending
#pragma unroll
        for (int kk = 0; kk < 8; kk++) {
            float af[8], bf[4];
#pragma unroll
            for (int i = 0; i < 8; i++) af[i] = As[buf][kk][tm + i];
#pragma unroll
            for (int j = 0; j < 4; j++) bf[j] = Bs[buf][kk][tn + j];
#pragma unroll
            for (int i = 0; i < 8; i++)
#pragma unroll
                for (int j = 0; j < 4; j++)
                    acc[i][j] = fmaf(af[i], bf[j], acc[i][j]);
        }

        // Eigen ST balanced kc=232 panel boundary (every 29 tiles of 8):
        // boundaries at kt+1 = 29, 58, ..., 261 (9 panels of 232); the final
        // 224-wide panel (tiles 261..288) is flushed in the epilogue.
        // fl(0 + P1) = P1 exactly, so panel 0 matches Eigen's first-panel
        // beta=0 store.
        if (((kt + 1) % 29) == 0) {
#pragma unroll
            for (int i = 0; i < 8; i++)
#pragma unroll
                for (int j = 0; j < 4; j++) {
                    tot[i][j] = __fadd_rn(tot[i][j], acc[i][j]);
                    acc[i][j] = 0.f;
                }
        }

        if (have_next) {
            As[nb][a_k4 + 0][a_row] = av.x;
            As[nb][a_k4 + 1][a_row] = av.y;
            As[nb][a_k4 + 2][a_row] = av.z;
            As[nb][a_k4 + 3][a_row] = av.w;
            if (tid < 128) {
                Bs[nb][a_k4 + 0][a_row] = bv.x;
                Bs[nb][a_k4 + 1][a_row] = bv.y;
                Bs[nb][a_k4 + 2][a_row] = bv.z;
                Bs[nb][a_k4 + 3][a_row] = bv.w;
            }
        }
        __syncthreads();
        buf = nb;
    }

    // epilogue: flush final (224-wide) panel, add bias once, store.
    const int col = nbase + tn;
    if (col < HH) {
        float4 bias = *(const float4*)(b1 + col);
#pragma unroll
        for (int i = 0; i < 8; i++) {
            int r = bm * 128 + tm + i;
            float4 v;
            v.x = __fadd_rn(__fadd_rn(tot[i][0], acc[i][0]), bias.x);
            v.y = __fadd_rn(__fadd_rn(tot[i][1], acc[i][1]), bias.y);
            v.z = __fadd_rn(__fadd_rn(tot[i][2], acc[i][2]), bias.z);
            v.w = __fadd_rn(__fadd_rn(tot[i][3], acc[i][3]), bias.w);
            *(float4*)(g_cur1 + (size_t)r * HH + col) = v;
        }
    }
}

// ---------------------------------------------------------------------------
// Kernel 2: per-batch temporal scan. One CTA per batch element b.
// Emission matched to XLA CPU (no fp contraction across HLO ops):
//   mem = fl( fl( fl(beta*mem) + cur ) - spk )         [rn mul/add/sub]
//   cur2[o] = ascending-h FMA chain of spk[h]*w2[o][h], then one +b2 add.
// cur2 ordering contributes only ~1e-6 rel (no spk2 flips ever observed).
// ---------------------------------------------------------------------------
#define W2PITCH 1001   // pad so lanes o=0..9 hit distinct banks

__global__ __launch_bounds__(256) void scan_kernel(
    const float* __restrict__ w2,
    const float* __restrict__ b2,
    const float* __restrict__ betap,
    float* __restrict__ out)
{
    __shared__ float w2s[OO * W2PITCH];   // 40 KB
    __shared__ float spkbuf[HH];          // 4 KB

    const int b   = blockIdx.x;
    const int tid = threadIdx.x;
    const float beta = *betap;

    // stage w2 into smem (row o at pitch 1001)
    for (int idx = tid; idx < OO * HH; idx += 256) {
        int o = idx / HH, h = idx - o * HH;
        w2s[o * W2PITCH + h] = w2[idx];
    }

    float mem1[4] = {0.f, 0.f, 0.f, 0.f};
    float spk1[4] = {0.f, 0.f, 0.f, 0.f};
    float mem2 = 0.f, spk2 = 0.f;          // meaningful for tid < 10
    float myb2 = (tid < OO) ? b2[tid] : 0.f;

    const float* cur1b = g_cur1 + (size_t)b * TT * HH;
    __syncthreads();

    for (int t = 0; t < TT; t++) {
        const float* c = cur1b + t * HH;

#pragma unroll
        for (int j = 0; j < 4; j++) {
            int h = tid + j * 256;
            if (h < HH) {
                float cur = __ldg(c + h);
                // mem = fl(fl(fl(beta*mem) + cur) - spk)   (XLA rn op order)
                float m = __fsub_rn(__fadd_rn(__fmul_rn(beta, mem1[j]), cur), spk1[j]);
                mem1[j] = m;
                float s = (m > 1.0f) ? 1.f : 0.f;   // (mem-1)>0 <=> mem>1 (exact)
                spk1[j] = s;
                spkbuf[h] = s;
            }
        }
        __syncthreads();

        if (tid < OO) {
            // ascending-h single-accumulator FMA chain.
            float acc = 0.f;
            const float* wrow = w2s + tid * W2PITCH;
            for (int h = 0; h < HH; h += 4) {
                acc = fmaf(spkbuf[h + 0], wrow[h + 0], acc);
                acc = fmaf(spkbuf[h + 1], wrow[h + 1], acc);
                acc = fmaf(spkbuf[h + 2], wrow[h + 2], acc);
                acc = fmaf(spkbuf[h + 3], wrow[h + 3], acc);
            }
            float cur2 = __fadd_rn(acc, myb2);
            float m2 = __fsub_rn(__fadd_rn(__fmul_rn(beta, mem2), cur2), spk2);
            mem2 = m2;
            spk2 = (m2 > 1.0f) ? 1.f : 0.f;
            size_t idx = (size_t)(t * BB + b) * OO + tid;
            out[idx] = spk2;                                   // spk_rec
            out[(size_t)TT * BB * OO + idx] = mem2;            // mem_rec
        }
        __syncthreads();   // spkbuf reused next iteration
    }
}

// ---------------------------------------------------------------------------
extern "C" void kernel_launch(void* const* d_in, const int* in_sizes, int n_in,
                              void* d_out, int out_size)
{
    (void)in_sizes; (void)n_in; (void)out_size;
    const float* data = (const float*)d_in[0];   // [256,100,2,34,34] fp32
    const float* w1   = (const float*)d_in[1];   // [1000,2312]
    const float* b1   = (const float*)d_in[2];   // [1000]
    const float* w2   = (const float*)d_in[3];   // [10,1000]
    const float* b2   = (const float*)d_in[4];   // [10]
    const float* beta = (const float*)d_in[5];   // scalar
    float* out = (float*)d_out;                  // [2,100,256,10]

    dim3 g1(16, 200);   // N tiles x M tiles
    gemm1_kernel<<<g1, 256>>>(data, w1, b1);
    scan_kernel<<<BB, 256>>>(w2, b2, beta, out);
}

// round 9
// speedup vs baseline: 1.1796x; 1.1796x over previous
#include <cuda_runtime.h>

// Problem dims (fixed for SNN_Vanilla_11630771437863)
#define BB 256      // batch
#define TT 100      // timesteps
#define DD 2312     // input dim (2*34*34)
#define HH 1000     // hidden
#define OO 10       // output

// Scratch: cur1_all stored [B][T][H] (b-major so scan CTA b reads contiguously)
__device__ float g_cur1[(size_t)BB * TT * HH];   // 102.4 MB

// ---------------------------------------------------------------------------
// Kernel 1 (NUMERICS FROZEN — R8 passing order, do not change):
// cur1[r][n] = sum_k A[r][k] * W1[n][k] + b1[n]
// Eigen SINGLE-THREADED gebp blocking (aarch64 NEON mr=12/nr=4, l1=16KB):
//   balanced kc = 232; panels 9 x 232 + 224 (boundary every 29 BK=8 tiles)
//   within a panel: single-accumulator ascending-k FMA chain from 0
//   panels summed sequentially; ONE fp32 bias add at the end.
// ---------------------------------------------------------------------------
__global__ __launch_bounds__(256) void gemm1_kernel(
    const float* __restrict__ A,
    const float* __restrict__ W,
    const float* __restrict__ b1)
{
    __shared__ float As[2][8][128];
    __shared__ float Bs[2][8][64];

    const int bm = blockIdx.y;          // 0..199
    const int bn = blockIdx.x;          // 0..15
    const int tid = threadIdx.x;

    const int tm = (tid >> 4) * 8;      // M offset in tile
    const int tn = (tid & 15) * 4;      // N offset in tile

    const int a_row = tid >> 1;         // 0..127
    const int a_k4  = (tid & 1) * 4;    // 0 or 4
    const int nbase = bn * 64;

    const float* Ab = A + (size_t)(bm * 128) * DD;

    float tot[8][4];   // running sum over panels
    float acc[8][4];   // current panel partial
#pragma unroll
    for (int i = 0; i < 8; i++)
#pragma unroll
        for (int j = 0; j < 4; j++) { tot[i][j] = 0.f; acc[i][j] = 0.f; }

    // prologue: load k-tile 0 into buffer 0
    {
        float4 av = *(const float4*)(Ab + (size_t)a_row * DD + a_k4);
        As[0][a_k4 + 0][a_row] = av.x;
        As[0][a_k4 + 1][a_row] = av.y;
        As[0][a_k4 + 2][a_row] = av.z;
        As[0][a_k4 + 3][a_row] = av.w;
        if (tid < 128) {
            int n = nbase + a_row;
            float4 bv = make_float4(0.f, 0.f, 0.f, 0.f);
            if (n < HH) bv = *(const float4*)(W + (size_t)n * DD + a_k4);
            Bs[0][a_k4 + 0][a_row] = bv.x;
            Bs[0][a_k4 + 1][a_row] = bv.y;
            Bs[0][a_k4 + 2][a_row] = bv.z;
            Bs[0][a_k4 + 3][a_row] = bv.w;
        }
    }
    __syncthreads();

    const int KITER = DD / 8;   // 289 exactly
    int buf = 0;
    for (int kt = 0; kt < KITER; ++kt) {
        const int nb = buf ^ 1;
        float4 av, bv;
        bool have_next = (kt + 1 < KITER);
        if (have_next) {
            int k0 = (kt + 1) * 8;
            av = *(const float4*)(Ab + (size_t)a_row * DD + k0 + a_k4);
            if (tid < 128) {
                int n = nbase + a_row;
                bv = make_float4(0.f, 0.f, 0.f, 0.f);
                if (n < HH) bv = *(const float4*)(W + (size_t)n * DD + k0 + a_k4);
            }
        }

        // compute on current buffer: kk ascending -> k strictly ascending
#pragma unroll
        for (int kk = 0; kk < 8; kk++) {
            float af[8], bf[4];
#pragma unroll
            for (int i = 0; i < 8; i++) af[i] = As[buf][kk][tm + i];
#pragma unroll
            for (int j = 0; j < 4; j++) bf[j] = Bs[buf][kk][tn + j];
#pragma unroll
            for (int i = 0; i < 8; i++)
#pragma unroll
                for (int j = 0; j < 4; j++)
                    acc[i][j] = fmaf(af[i], bf[j], acc[i][j]);
        }

        // Eigen ST balanced kc=232 panel boundary (every 29 tiles of 8).
        if (((kt + 1) % 29) == 0) {
#pragma unroll
            for (int i = 0; i < 8; i++)
#pragma unroll
                for (int j = 0; j < 4; j++) {
                    tot[i][j] = __fadd_rn(tot[i][j], acc[i][j]);
                    acc[i][j] = 0.f;
                }
        }

        if (have_next) {
            As[nb][a_k4 + 0][a_row] = av.x;
            As[nb][a_k4 + 1][a_row] = av.y;
            As[nb][a_k4 + 2][a_row] = av.z;
            As[nb][a_k4 + 3][a_row] = av.w;
            if (tid < 128) {
                Bs[nb][a_k4 + 0][a_row] = bv.x;
                Bs[nb][a_k4 + 1][a_row] = bv.y;
                Bs[nb][a_k4 + 2][a_row] = bv.z;
                Bs[nb][a_k4 + 3][a_row] = bv.w;
            }
        }
        __syncthreads();
        buf = nb;
    }

    // epilogue: flush final (224-wide) panel, add bias once, store.
    const int col = nbase + tn;
    if (col < HH) {
        float4 bias = *(const float4*)(b1 + col);
#pragma unroll
        for (int i = 0; i < 8; i++) {
            int r = bm * 128 + tm + i;
            float4 v;
            v.x = __fadd_rn(__fadd_rn(tot[i][0], acc[i][0]), bias.x);
            v.y = __fadd_rn(__fadd_rn(tot[i][1], acc[i][1]), bias.y);
            v.z = __fadd_rn(__fadd_rn(tot[i][2], acc[i][2]), bias.z);
            v.w = __fadd_rn(__fadd_rn(tot[i][3], acc[i][3]), bias.w);
            *(float4*)(g_cur1 + (size_t)r * HH + col) = v;
        }
    }
}

// ---------------------------------------------------------------------------
// Kernel 2: per-batch temporal scan. One CTA per batch element b.
// Recurrence bits FROZEN (rn mul/add/sub, matches R8 pass):
//   mem = fl( fl( fl(beta*mem) + cur ) - spk )
// cur2: warp-tree + smem reduction (order PROVEN irrelevant to the flip
// signature in R4-vs-R5; contributes ~1e-6 rel only). This removes the
// 1000-long serial FMA chain that made the scan 624us.
// Software pipeline: prefetch t+1's cur1 slice during t's reduction.
// ---------------------------------------------------------------------------
__global__ __launch_bounds__(256) void scan_kernel(
    const float* __restrict__ w2,
    const float* __restrict__ b2,
    const float* __restrict__ betap,
    float* __restrict__ out)
{
    const int b   = blockIdx.x;
    const int tid = threadIdx.x;
    const int warp = tid >> 5;
    const int lane = tid & 31;
    const float beta = *betap;

    __shared__ float red[8][16];   // 8 warps x 10 partials (padded)

    // register-resident w2 slices for this thread's h values
    float w2r[4][OO];
#pragma unroll
    for (int j = 0; j < 4; j++) {
        int h = tid + j * 256;
        bool v = (h < HH);
#pragma unroll
        for (int o = 0; o < OO; o++)
            w2r[j][o] = v ? w2[o * HH + h] : 0.f;
    }

    float mem1[4] = {0.f, 0.f, 0.f, 0.f};
    float spk1[4] = {0.f, 0.f, 0.f, 0.f};
    float mem2 = 0.f, spk2 = 0.f;          // meaningful for tid < 10
    float myb2 = (tid < OO) ? b2[tid] : 0.f;

    const float* cur1b = g_cur1 + (size_t)b * TT * HH;

    // prefetch t=0 slice
    float cur[4];
#pragma unroll
    for (int j = 0; j < 4; j++) {
        int h = tid + j * 256;
        cur[j] = (h < HH) ? __ldg(cur1b + h) : 0.f;
    }

    for (int t = 0; t < TT; t++) {
        float part[OO];
#pragma unroll
        for (int o = 0; o < OO; o++) part[o] = 0.f;

#pragma unroll
        for (int j = 0; j < 4; j++) {
            // mem = fl(fl(fl(beta*mem) + cur) - spk)   (frozen rn op order)
            float m = __fsub_rn(__fadd_rn(__fmul_rn(beta, mem1[j]), cur[j]), spk1[j]);
            mem1[j] = m;
            float s = (m > 1.0f) ? 1.f : 0.f;   // (mem-1)>0 <=> mem>1 (exact)
            spk1[j] = s;
#pragma unroll
            for (int o = 0; o < OO; o++)
                part[o] = fmaf(s, w2r[j][o], part[o]);   // products exact (s in {0,1})
        }

        // prefetch next timestep's cur1 slice (hides L2 latency behind the
        // reduction below)
        if (t + 1 < TT) {
            const float* cn = cur1b + (t + 1) * HH;
#pragma unroll
            for (int j = 0; j < 4; j++) {
                int h = tid + j * 256;
                cur[j] = (h < HH) ? __ldg(cn + h) : 0.f;
            }
        }

        // intra-warp tree reduction (10 independent shuffle chains)
#pragma unroll
        for (int off = 16; off > 0; off >>= 1) {
#pragma unroll
            for (int o = 0; o < OO; o++)
                part[o] += __shfl_xor_sync(0xffffffffu, part[o], off);
        }
        if (lane == 0) {
#pragma unroll
            for (int o = 0; o < OO; o++) red[warp][o] = part[o];
        }
        __syncthreads();

        if (tid < OO) {
            float cur2 = 0.f;
#pragma unroll
            for (int w = 0; w < 8; w++) cur2 = __fadd_rn(cur2, red[w][tid]);
            cur2 = __fadd_rn(cur2, myb2);
            float m2 = __fsub_rn(__fadd_rn(__fmul_rn(beta, mem2), cur2), spk2);
            mem2 = m2;
            spk2 = (m2 > 1.0f) ? 1.f : 0.f;
            size_t idx = (size_t)(t * BB + b) * OO + tid;
            out[idx] = spk2;                                   // spk_rec
            out[(size_t)TT * BB * OO + idx] = mem2;            // mem_rec
        }
        __syncthreads();   // red[] reused next iteration
    }
}

// ---------------------------------------------------------------------------
extern "C" void kernel_launch(void* const* d_in, const int* in_sizes, int n_in,
                              void* d_out, int out_size)
{
    (void)in_sizes; (void)n_in; (void)out_size;
    const float* data = (const float*)d_in[0];   // [256,100,2,34,34] fp32
    const float* w1   = (const float*)d_in[1];   // [1000,2312]
    const float* b1   = (const float*)d_in[2];   // [1000]
    const float* w2   = (const float*)d_in[3];   // [10,1000]
    const float* b2   = (const float*)d_in[4];   // [10]
    const float* beta = (const float*)d_in[5];   // scalar
    float* out = (float*)d_out;                  // [2,100,256,10]

    dim3 g1(16, 200);   // N tiles x M tiles
    gemm1_kernel<<<g1, 256>>>(data, w1, b1);
    scan_kernel<<<BB, 256>>>(w2, b2, beta, out);
}

// round 10
// speedup vs baseline: 1.3144x; 1.1143x over previous
#include <cuda_runtime.h>

// Problem dims (fixed for SNN_Vanilla_11630771437863)
#define BB 256      // batch
#define TT 100      // timesteps
#define DD 2312     // input dim (2*34*34)
#define HH 1000     // hidden
#define OO 10       // output

typedef unsigned long long ull;

// Scratch: cur1_all stored [B][T][H] (b-major so scan CTA b reads contiguously)
__device__ float g_cur1[(size_t)BB * TT * HH];   // 102.4 MB

// Packed f32x2 helpers (sm_103a). fma.rn.f32x2 / add.rn.f32x2 are two
// INDEPENDENT IEEE-754 rn fp32 ops per instruction -> bitwise identical to
// two scalar fmaf/__fadd_rn. Numerics of the frozen Eigen order preserved.
__device__ __forceinline__ ull fma2(ull a, ull b, ull c) {
    ull d;
    asm("fma.rn.f32x2 %0, %1, %2, %3;" : "=l"(d) : "l"(a), "l"(b), "l"(c));
    return d;
}
__device__ __forceinline__ ull add2(ull a, ull b) {
    ull d;
    asm("add.rn.f32x2 %0, %1, %2;" : "=l"(d) : "l"(a), "l"(b));
    return d;
}
__device__ __forceinline__ ull dup2(float x) {
    ull d;
    unsigned xi = __float_as_uint(x);
    asm("mov.b64 %0, {%1, %1};" : "=l"(d) : "r"(xi));
    return d;
}
__device__ __forceinline__ float lo32(ull v) { return __uint_as_float((unsigned)v); }
__device__ __forceinline__ float hi32(ull v) { return __uint_as_float((unsigned)(v >> 32)); }

// ---------------------------------------------------------------------------
// Kernel 1 (NUMERICS FROZEN — R8 passing order, bitwise preserved):
// cur1[r][n] = sum_k A[r][k] * W1[n][k] + b1[n]
// Eigen ST gebp: balanced kc = 232; panels 9 x 232 + 224 (boundary every 29
// BK=8 tiles); ascending-k single-accumulator chain per panel; panels summed
// sequentially; one fp32 bias add.
// FFMA2 version: accumulators packed over M pairs (rows tm+2p, tm+2p+1);
// per (row,col) the chain is the SAME sequence of rn-FMAs -> bit-identical.
// ---------------------------------------------------------------------------
__global__ __launch_bounds__(256) void gemm1_kernel(
    const float* __restrict__ A,
    const float* __restrict__ W,
    const float* __restrict__ b1)
{
    __shared__ float As[2][8][128];
    __shared__ float Bs[2][8][64];

    const int bm = blockIdx.y;          // 0..199
    const int bn = blockIdx.x;          // 0..15
    const int tid = threadIdx.x;

    const int tm = (tid >> 4) * 8;      // M offset in tile (multiple of 8)
    const int tn = (tid & 15) * 4;      // N offset in tile

    const int a_row = tid >> 1;         // 0..127
    const int a_k4  = (tid & 1) * 4;    // 0 or 4
    const int nbase = bn * 64;

    const float* Ab = A + (size_t)(bm * 128) * DD;

    ull tot2[4][4];   // running sum over panels, rows (2p,2p+1) x col j
    ull acc2[4][4];   // current panel partial
#pragma unroll
    for (int p = 0; p < 4; p++)
#pragma unroll
        for (int j = 0; j < 4; j++) { tot2[p][j] = 0ull; acc2[p][j] = 0ull; }

    // prologue: load k-tile 0 into buffer 0
    {
        float4 av = *(const float4*)(Ab + (size_t)a_row * DD + a_k4);
        As[0][a_k4 + 0][a_row] = av.x;
        As[0][a_k4 + 1][a_row] = av.y;
        As[0][a_k4 + 2][a_row] = av.z;
        As[0][a_k4 + 3][a_row] = av.w;
        if (tid < 128) {
            int n = nbase + a_row;
            float4 bv = make_float4(0.f, 0.f, 0.f, 0.f);
            if (n < HH) bv = *(const float4*)(W + (size_t)n * DD + a_k4);
            Bs[0][a_k4 + 0][a_row] = bv.x;
            Bs[0][a_k4 + 1][a_row] = bv.y;
            Bs[0][a_k4 + 2][a_row] = bv.z;
            Bs[0][a_k4 + 3][a_row] = bv.w;
        }
    }
    __syncthreads();

    const int KITER = DD / 8;   // 289 exactly
    int buf = 0;
    for (int kt = 0; kt < KITER; ++kt) {
        const int nb = buf ^ 1;
        float4 av, bv;
        bool have_next = (kt + 1 < KITER);
        if (have_next) {
            int k0 = (kt + 1) * 8;
            av = *(const float4*)(Ab + (size_t)a_row * DD + k0 + a_k4);
            if (tid < 128) {
                int n = nbase + a_row;
                bv = make_float4(0.f, 0.f, 0.f, 0.f);
                if (n < HH) bv = *(const float4*)(W + (size_t)n * DD + k0 + a_k4);
            }
        }

        // compute on current buffer: kk ascending -> k strictly ascending.
        // a pairs via LDS.64 (rows 2p,2p+1 contiguous, 8B aligned);
        // b duplicated into both lanes (mov.b64 on ALU pipe).
#pragma unroll
        for (int kk = 0; kk < 8; kk++) {
            ull a2[4], b2[4];
#pragma unroll
            for (int p = 0; p < 4; p++)
                a2[p] = *(const ull*)&As[buf][kk][tm + 2 * p];
#pragma unroll
            for (int j = 0; j < 4; j++)
                b2[j] = dup2(Bs[buf][kk][tn + j]);
#pragma unroll
            for (int p = 0; p < 4; p++)
#pragma unroll
                for (int j = 0; j < 4; j++)
                    acc2[p][j] = fma2(a2[p], b2[j], acc2[p][j]);
        }

        // Eigen ST balanced kc=232 panel boundary (every 29 tiles of 8).
        // add.rn.f32x2 = two independent rn adds (bit-identical to scalar).
        if (((kt + 1) % 29) == 0) {
#pragma unroll
            for (int p = 0; p < 4; p++)
#pragma unroll
                for (int j = 0; j < 4; j++) {
                    tot2[p][j] = add2(tot2[p][j], acc2[p][j]);
                    acc2[p][j] = 0ull;
                }
        }

        if (have_next) {
            As[nb][a_k4 + 0][a_row] = av.x;
            As[nb][a_k4 + 1][a_row] = av.y;
            As[nb][a_k4 + 2][a_row] = av.z;
            As[nb][a_k4 + 3][a_row] = av.w;
            if (tid < 128) {
                Bs[nb][a_k4 + 0][a_row] = bv.x;
                Bs[nb][a_k4 + 1][a_row] = bv.y;
                Bs[nb][a_k4 + 2][a_row] = bv.z;
                Bs[nb][a_k4 + 3][a_row] = bv.w;
            }
        }
        __syncthreads();
        buf = nb;
    }

    // epilogue: flush final (224-wide) panel, add bias once, store.
    // Same op order as R8: fl(fl(tot + acc) + bias), per element.
    const int col = nbase + tn;
    if (col < HH) {
        float4 bias = *(const float4*)(b1 + col);
#pragma unroll
        for (int p = 0; p < 4; p++) {
            float4 vlo, vhi;
            {
                float t0 = __fadd_rn(lo32(tot2[p][0]), lo32(acc2[p][0]));
                float t1 = __fadd_rn(lo32(tot2[p][1]), lo32(acc2[p][1]));
                float t2 = __fadd_rn(lo32(tot2[p][2]), lo32(acc2[p][2]));
                float t3 = __fadd_rn(lo32(tot2[p][3]), lo32(acc2[p][3]));
                vlo.x = __fadd_rn(t0, bias.x);
                vlo.y = __fadd_rn(t1, bias.y);
                vlo.z = __fadd_rn(t2, bias.z);
                vlo.w = __fadd_rn(t3, bias.w);
            }
            {
                float t0 = __fadd_rn(hi32(tot2[p][0]), hi32(acc2[p][0]));
                float t1 = __fadd_rn(hi32(tot2[p][1]), hi32(acc2[p][1]));
                float t2 = __fadd_rn(hi32(tot2[p][2]), hi32(acc2[p][2]));
                float t3 = __fadd_rn(hi32(tot2[p][3]), hi32(acc2[p][3]));
                vhi.x = __fadd_rn(t0, bias.x);
                vhi.y = __fadd_rn(t1, bias.y);
                vhi.z = __fadd_rn(t2, bias.z);
                vhi.w = __fadd_rn(t3, bias.w);
            }
            int rlo = bm * 128 + tm + 2 * p;
            *(float4*)(g_cur1 + (size_t)rlo * HH + col) = vlo;
            *(float4*)(g_cur1 + (size_t)(rlo + 1) * HH + col) = vhi;
        }
    }
}

// ---------------------------------------------------------------------------
// Kernel 2: per-batch temporal scan (R9 version, 76us — unchanged).
// Recurrence bits FROZEN (rn mul/add/sub):
//   mem = fl( fl( fl(beta*mem) + cur ) - spk )
// ---------------------------------------------------------------------------
__global__ __launch_bounds__(256) void scan_kernel(
    const float* __restrict__ w2,
    const float* __restrict__ b2,
    const float* __restrict__ betap,
    float* __restrict__ out)
{
    const int b   = blockIdx.x;
    const int tid = threadIdx.x;
    const int warp = tid >> 5;
    const int lane = tid & 31;
    const float beta = *betap;

    __shared__ float red[8][16];   // 8 warps x 10 partials (padded)

    // register-resident w2 slices for this thread's h values
    float w2r[4][OO];
#pragma unroll
    for (int j = 0; j < 4; j++) {
        int h = tid + j * 256;
        bool v = (h < HH);
#pragma unroll
        for (int o = 0; o < OO; o++)
            w2r[j][o] = v ? w2[o * HH + h] : 0.f;
    }

    float mem1[4] = {0.f, 0.f, 0.f, 0.f};
    float spk1[4] = {0.f, 0.f, 0.f, 0.f};
    float mem2 = 0.f, spk2 = 0.f;          // meaningful for tid < 10
    float myb2 = (tid < OO) ? b2[tid] : 0.f;

    const float* cur1b = g_cur1 + (size_t)b * TT * HH;

    // prefetch t=0 slice
    float cur[4];
#pragma unroll
    for (int j = 0; j < 4; j++) {
        int h = tid + j * 256;
        cur[j] = (h < HH) ? __ldg(cur1b + h) : 0.f;
    }

    for (int t = 0; t < TT; t++) {
        float part[OO];
#pragma unroll
        for (int o = 0; o < OO; o++) part[o] = 0.f;

#pragma unroll
        for (int j = 0; j < 4; j++) {
            // mem = fl(fl(fl(beta*mem) + cur) - spk)   (frozen rn op order)
            float m = __fsub_rn(__fadd_rn(__fmul_rn(beta, mem1[j]), cur[j]), spk1[j]);
            mem1[j] = m;
            float s = (m > 1.0f) ? 1.f : 0.f;   // (mem-1)>0 <=> mem>1 (exact)
            spk1[j] = s;
#pragma unroll
            for (int o = 0; o < OO; o++)
                part[o] = fmaf(s, w2r[j][o], part[o]);   // products exact (s in {0,1})
        }

        // prefetch next timestep's cur1 slice
        if (t + 1 < TT) {
            const float* cn = cur1b + (t + 1) * HH;
#pragma unroll
            for (int j = 0; j < 4; j++) {
                int h = tid + j * 256;
                cur[j] = (h < HH) ? __ldg(cn + h) : 0.f;
            }
        }

        // intra-warp tree reduction (10 independent shuffle chains)
#pragma unroll
        for (int off = 16; off > 0; off >>= 1) {
#pragma unroll
            for (int o = 0; o < OO; o++)
                part[o] += __shfl_xor_sync(0xffffffffu, part[o], off);
        }
        if (lane == 0) {
#pragma unroll
            for (int o = 0; o < OO; o++) red[warp][o] = part[o];
        }
        __syncthreads();

        if (tid < OO) {
            float cur2 = 0.f;
#pragma unroll
            for (int w = 0; w < 8; w++) cur2 = __fadd_rn(cur2, red[w][tid]);
            cur2 = __fadd_rn(cur2, myb2);
            float m2 = __fsub_rn(__fadd_rn(__fmul_rn(beta, mem2), cur2), spk2);
            mem2 = m2;
            spk2 = (m2 > 1.0f) ? 1.f : 0.f;
            size_t idx = (size_t)(t * BB + b) * OO + tid;
            out[idx] = spk2;                                   // spk_rec
            out[(size_t)TT * BB * OO + idx] = mem2;            // mem_rec
        }
        __syncthreads();   // red[] reused next iteration
    }
}

// ---------------------------------------------------------------------------
extern "C" void kernel_launch(void* const* d_in, const int* in_sizes, int n_in,
                              void* d_out, int out_size)
{
    (void)in_sizes; (void)n_in; (void)out_size;
    const float* data = (const float*)d_in[0];   // [256,100,2,34,34] fp32
    const float* w1   = (const float*)d_in[1];   // [1000,2312]
    const float* b1   = (const float*)d_in[2];   // [1000]
    const float* w2   = (const float*)d_in[3];   // [10,1000]
    const float* b2   = (const float*)d_in[4];   // [10]
    const float* beta = (const float*)d_in[5];   // scalar
    float* out = (float*)d_out;                  // [2,100,256,10]

    dim3 g1(16, 200);   // N tiles x M tiles
    gemm1_kernel<<<g1, 256>>>(data, w1, b1);
    scan_kernel<<<BB, 256>>>(w2, b2, beta, out);
}

// round 11
// speedup vs baseline: 1.3370x; 1.0172x over previous
#include <cuda_runtime.h>

// Problem dims (fixed for SNN_Vanilla_11630771437863)
#define BB 256      // batch
#define TT 100      // timesteps
#define DD 2312     // input dim (2*34*34)
#define HH 1000     // hidden
#define OO 10       // output

typedef unsigned long long ull;

// Scratch: cur1_all stored [B][T][H] (b-major so scan CTA b reads contiguously)
__device__ float g_cur1[(size_t)BB * TT * HH];   // 102.4 MB

// Packed f32x2 helpers (sm_103a). fma.rn.f32x2 / add.rn.f32x2 are two
// INDEPENDENT IEEE-754 rn fp32 ops per instruction -> bitwise identical to
// two scalar fmaf/__fadd_rn. Numerics of the frozen Eigen order preserved.
__device__ __forceinline__ ull fma2(ull a, ull b, ull c) {
    ull d;
    asm("fma.rn.f32x2 %0, %1, %2, %3;" : "=l"(d) : "l"(a), "l"(b), "l"(c));
    return d;
}
__device__ __forceinline__ ull add2(ull a, ull b) {
    ull d;
    asm("add.rn.f32x2 %0, %1, %2;" : "=l"(d) : "l"(a), "l"(b));
    return d;
}
__device__ __forceinline__ ull dup2(float x) {
    ull d;
    unsigned xi = __float_as_uint(x);
    asm("mov.b64 %0, {%1, %1};" : "=l"(d) : "r"(xi));
    return d;
}
__device__ __forceinline__ float lo32(ull v) { return __uint_as_float((unsigned)v); }
__device__ __forceinline__ float hi32(ull v) { return __uint_as_float((unsigned)(v >> 32)); }

// ---------------------------------------------------------------------------
// Kernel 1 (NUMERICS FROZEN — R8 passing Eigen order, bitwise preserved):
// cur1[r][n] = sum_k A[r][k] * W1[n][k] + b1[n]
// Eigen ST gebp: balanced kc = 232; panels 9 x 232 + 224; ascending-k
// single-accumulator chain per panel; panels summed sequentially; one fp32
// bias add. FFMA2-packed over M pairs.
// BK=16 (halves barriers + loop overhead vs BK=8). kc=232 boundaries are not
// 16-aligned: flush MID-TILE (after kk=7) when kt%29==14 (kt=14,43,72,101,130)
// and END-OF-TILE when kt%29==28, kt!=144 (kt=28,57,86,115). Tail: tile 144
// is a zero-padded half tile (k=2304..2311 real, 2312..2319 zeros -> +0
// contributions, bit-harmless).
// ---------------------------------------------------------------------------
__global__ __launch_bounds__(256) void gemm1_kernel(
    const float* __restrict__ A,
    const float* __restrict__ W,
    const float* __restrict__ b1)
{
    __shared__ __align__(16) float As[2][16][128];  // 16 KB
    __shared__ __align__(16) float Bs[2][16][64];   //  8 KB

    const int bm = blockIdx.y;          // 0..199
    const int bn = blockIdx.x;          // 0..15
    const int tid = threadIdx.x;

    const int tm = (tid >> 4) * 8;      // M offset in tile (multiple of 8)
    const int tn = (tid & 15) * 4;      // N offset in tile

    const int a_row = tid >> 1;         // 0..127
    const int a_k4  = (tid & 1) * 4;    // 0 or 4
    const int w_row = tid >> 2;         // 0..63
    const int w_k4  = (tid & 3) * 4;    // 0,4,8,12
    const int nbase = bn * 64;
    const int wn    = nbase + w_row;    // W row this thread loads

    const float* Ar = A + (size_t)(bm * 128 + a_row) * DD;   // this thread's A row
    const float* Wr = W + (size_t)wn * DD;

    ull tot2[4][4];   // running sum over panels, rows (2p,2p+1) x col j
    ull acc2[4][4];   // current panel partial
#pragma unroll
    for (int p = 0; p < 4; p++)
#pragma unroll
        for (int j = 0; j < 4; j++) { tot2[p][j] = 0ull; acc2[p][j] = 0ull; }

    // prologue: load k-tile 0 (k=0..15) into buffer 0
    {
        float4 av0 = *(const float4*)(Ar + a_k4);
        float4 av1 = *(const float4*)(Ar + 8 + a_k4);
        As[0][a_k4 + 0][a_row] = av0.x;
        As[0][a_k4 + 1][a_row] = av0.y;
        As[0][a_k4 + 2][a_row] = av0.z;
        As[0][a_k4 + 3][a_row] = av0.w;
        As[0][8 + a_k4 + 0][a_row] = av1.x;
        As[0][8 + a_k4 + 1][a_row] = av1.y;
        As[0][8 + a_k4 + 2][a_row] = av1.z;
        As[0][8 + a_k4 + 3][a_row] = av1.w;
        float4 bv = make_float4(0.f, 0.f, 0.f, 0.f);
        if (wn < HH) bv = *(const float4*)(Wr + w_k4);
        Bs[0][w_k4 + 0][w_row] = bv.x;
        Bs[0][w_k4 + 1][w_row] = bv.y;
        Bs[0][w_k4 + 2][w_row] = bv.z;
        Bs[0][w_k4 + 3][w_row] = bv.w;
    }
    __syncthreads();

    const int NT = 145;     // 144 full 16-wide tiles + 1 half tile
    int buf = 0;
    int pc = 0;             // kt % 29 maintained incrementally
    for (int kt = 0; kt < NT; ++kt) {
        const int nb = buf ^ 1;
        float4 av0, av1, bv;
        const bool have_next = (kt + 1 < NT);
        if (have_next) {
            const int k0 = (kt + 1) * 16;
            av0 = *(const float4*)(Ar + k0 + a_k4);     // always in-bounds (<=2311)
            av1 = make_float4(0.f, 0.f, 0.f, 0.f);
            if (k0 + 16 <= DD)                          // hi half valid?
                av1 = *(const float4*)(Ar + k0 + 8 + a_k4);
            bv = make_float4(0.f, 0.f, 0.f, 0.f);
            if (wn < HH && (k0 + w_k4 + 4 <= DD))
                bv = *(const float4*)(Wr + k0 + w_k4);
        }

        // ---- compute kk = 0..7 (k ascending) ----
#pragma unroll
        for (int kk = 0; kk < 8; kk++) {
            ull a2[4], b2[4];
#pragma unroll
            for (int p = 0; p < 4; p++)
                a2[p] = *(const ull*)&As[buf][kk][tm + 2 * p];
#pragma unroll
            for (int j = 0; j < 4; j++)
                b2[j] = dup2(Bs[buf][kk][tn + j]);
#pragma unroll
            for (int p = 0; p < 4; p++)
#pragma unroll
                for (int j = 0; j < 4; j++)
                    acc2[p][j] = fma2(a2[p], b2[j], acc2[p][j]);
        }

        // mid-tile panel boundary (k = 232m, m odd): kt = 14,43,72,101,130
        if (pc == 14) {
#pragma unroll
            for (int p = 0; p < 4; p++)
#pragma unroll
                for (int j = 0; j < 4; j++) {
                    tot2[p][j] = add2(tot2[p][j], acc2[p][j]);
                    acc2[p][j] = 0ull;
                }
        }

        // ---- compute kk = 8..15 ----
#pragma unroll
        for (int kk = 8; kk < 16; kk++) {
            ull a2[4], b2[4];
#pragma unroll
            for (int p = 0; p < 4; p++)
                a2[p] = *(const ull*)&As[buf][kk][tm + 2 * p];
#pragma unroll
            for (int j = 0; j < 4; j++)
                b2[j] = dup2(Bs[buf][kk][tn + j]);
#pragma unroll
            for (int p = 0; p < 4; p++)
#pragma unroll
                for (int j = 0; j < 4; j++)
                    acc2[p][j] = fma2(a2[p], b2[j], acc2[p][j]);
        }

        // end-of-tile panel boundary (k = 232m, m even): kt = 28,57,86,115
        // (NOT the tail tile kt=144, whose 144%29==28 is spurious)
        if (pc == 28 && kt != 144) {
#pragma unroll
            for (int p = 0; p < 4; p++)
#pragma unroll
                for (int j = 0; j < 4; j++) {
                    tot2[p][j] = add2(tot2[p][j], acc2[p][j]);
                    acc2[p][j] = 0ull;
                }
        }

        if (have_next) {
            As[nb][a_k4 + 0][a_row] = av0.x;
            As[nb][a_k4 + 1][a_row] = av0.y;
            As[nb][a_k4 + 2][a_row] = av0.z;
            As[nb][a_k4 + 3][a_row] = av0.w;
            As[nb][8 + a_k4 + 0][a_row] = av1.x;
            As[nb][8 + a_k4 + 1][a_row] = av1.y;
            As[nb][8 + a_k4 + 2][a_row] = av1.z;
            As[nb][8 + a_k4 + 3][a_row] = av1.w;
            Bs[nb][w_k4 + 0][w_row] = bv.x;
            Bs[nb][w_k4 + 1][w_row] = bv.y;
            Bs[nb][w_k4 + 2][w_row] = bv.z;
            Bs[nb][w_k4 + 3][w_row] = bv.w;
        }
        __syncthreads();
        buf = nb;
        if (++pc == 29) pc = 0;
    }

    // epilogue: flush final (224-wide) panel, add bias once, store.
    // Same op order as R8: fl(fl(tot + acc) + bias), per element.
    const int col = nbase + tn;
    if (col < HH) {
        float4 bias = *(const float4*)(b1 + col);
#pragma unroll
        for (int p = 0; p < 4; p++) {
            float4 vlo, vhi;
            {
                float t0 = __fadd_rn(lo32(tot2[p][0]), lo32(acc2[p][0]));
                float t1 = __fadd_rn(lo32(tot2[p][1]), lo32(acc2[p][1]));
                float t2 = __fadd_rn(lo32(tot2[p][2]), lo32(acc2[p][2]));
                float t3 = __fadd_rn(lo32(tot2[p][3]), lo32(acc2[p][3]));
                vlo.x = __fadd_rn(t0, bias.x);
                vlo.y = __fadd_rn(t1, bias.y);
                vlo.z = __fadd_rn(t2, bias.z);
                vlo.w = __fadd_rn(t3, bias.w);
            }
            {
                float t0 = __fadd_rn(hi32(tot2[p][0]), hi32(acc2[p][0]));
                float t1 = __fadd_rn(hi32(tot2[p][1]), hi32(acc2[p][1]));
                float t2 = __fadd_rn(hi32(tot2[p][2]), hi32(acc2[p][2]));
                float t3 = __fadd_rn(hi32(tot2[p][3]), hi32(acc2[p][3]));
                vhi.x = __fadd_rn(t0, bias.x);
                vhi.y = __fadd_rn(t1, bias.y);
                vhi.z = __fadd_rn(t2, bias.z);
                vhi.w = __fadd_rn(t3, bias.w);
            }
            int rlo = bm * 128 + tm + 2 * p;
            *(float4*)(g_cur1 + (size_t)rlo * HH + col) = vlo;
            *(float4*)(g_cur1 + (size_t)(rlo + 1) * HH + col) = vhi;
        }
    }
}

// ---------------------------------------------------------------------------
// Kernel 2: per-batch temporal scan (R9 version, 76us — unchanged).
// Recurrence bits FROZEN (rn mul/add/sub):
//   mem = fl( fl( fl(beta*mem) + cur ) - spk )
// ---------------------------------------------------------------------------
__global__ __launch_bounds__(256) void scan_kernel(
    const float* __restrict__ w2,
    const float* __restrict__ b2,
    const float* __restrict__ betap,
    float* __restrict__ out)
{
    const int b   = blockIdx.x;
    const int tid = threadIdx.x;
    const int warp = tid >> 5;
    const int lane = tid & 31;
    const float beta = *betap;

    __shared__ float red[8][16];   // 8 warps x 10 partials (padded)

    // register-resident w2 slices for this thread's h values
    float w2r[4][OO];
#pragma unroll
    for (int j = 0; j < 4; j++) {
        int h = tid + j * 256;
        bool v = (h < HH);
#pragma unroll
        for (int o = 0; o < OO; o++)
            w2r[j][o] = v ? w2[o * HH + h] : 0.f;
    }

    float mem1[4] = {0.f, 0.f, 0.f, 0.f};
    float spk1[4] = {0.f, 0.f, 0.f, 0.f};
    float mem2 = 0.f, spk2 = 0.f;          // meaningful for tid < 10
    float myb2 = (tid < OO) ? b2[tid] : 0.f;

    const float* cur1b = g_cur1 + (size_t)b * TT * HH;

    // prefetch t=0 slice
    float cur[4];
#pragma unroll
    for (int j = 0; j < 4; j++) {
        int h = tid + j * 256;
        cur[j] = (h < HH) ? __ldg(cur1b + h) : 0.f;
    }

    for (int t = 0; t < TT; t++) {
        float part[OO];
#pragma unroll
        for (int o = 0; o < OO; o++) part[o] = 0.f;

#pragma unroll
        for (int j = 0; j < 4; j++) {
            // mem = fl(fl(fl(beta*mem) + cur) - spk)   (frozen rn op order)
            float m = __fsub_rn(__fadd_rn(__fmul_rn(beta, mem1[j]), cur[j]), spk1[j]);
            mem1[j] = m;
            float s = (m > 1.0f) ? 1.f : 0.f;   // (mem-1)>0 <=> mem>1 (exact)
            spk1[j] = s;
#pragma unroll
            for (int o = 0; o < OO; o++)
                part[o] = fmaf(s, w2r[j][o], part[o]);   // products exact (s in {0,1})
        }

        // prefetch next timestep's cur1 slice
        if (t + 1 < TT) {
            const float* cn = cur1b + (t + 1) * HH;
#pragma unroll
            for (int j = 0; j < 4; j++) {
                int h = tid + j * 256;
                cur[j] = (h < HH) ? __ldg(cn + h) : 0.f;
            }
        }

        // intra-warp tree reduction (10 independent shuffle chains)
#pragma unroll
        for (int off = 16; off > 0; off >>= 1) {
#pragma unroll
            for (int o = 0; o < OO; o++)
                part[o] += __shfl_xor_sync(0xffffffffu, part[o], off);
        }
        if (lane == 0) {
#pragma unroll
            for (int o = 0; o < OO; o++) red[warp][o] = part[o];
        }
        __syncthreads();

        if (tid < OO) {
            float cur2 = 0.f;
#pragma unroll
            for (int w = 0; w < 8; w++) cur2 = __fadd_rn(cur2, red[w][tid]);
            cur2 = __fadd_rn(cur2, myb2);
            float m2 = __fsub_rn(__fadd_rn(__fmul_rn(beta, mem2), cur2), spk2);
            mem2 = m2;
            spk2 = (m2 > 1.0f) ? 1.f : 0.f;
            size_t idx = (size_t)(t * BB + b) * OO + tid;
            out[idx] = spk2;                                   // spk_rec
            out[(size_t)TT * BB * OO + idx] = mem2;            // mem_rec
        }
        __syncthreads();   // red[] reused next iteration
    }
}

// ---------------------------------------------------------------------------
extern "C" void kernel_launch(void* const* d_in, const int* in_sizes, int n_in,
                              void* d_out, int out_size)
{
    (void)in_sizes; (void)n_in; (void)out_size;
    const float* data = (const float*)d_in[0];   // [256,100,2,34,34] fp32
    const float* w1   = (const float*)d_in[1];   // [1000,2312]
    const float* b1   = (const float*)d_in[2];   // [1000]
    const float* w2   = (const float*)d_in[3];   // [10,1000]
    const float* b2   = (const float*)d_in[4];   // [10]
    const float* beta = (const float*)d_in[5];   // scalar
    float* out = (float*)d_out;                  // [2,100,256,10]

    dim3 g1(16, 200);   // N tiles x M tiles
    gemm1_kernel<<<g1, 256>>>(data, w1, b1);
    scan_kernel<<<BB, 256>>>(w2, b2, beta, out);
}